// round 1
// baseline (speedup 1.0000x reference)
#include <cuda_runtime.h>
#include <cuda_bf16.h>
#include <cuda_fp16.h>
#include <stdint.h>

#define N_TOK   8192
#define HIDDEN  1024
#define LATENT  16384
#define TOPK    32
#define NCAND   64

// ---------------- static device scratch (no allocations allowed) ----------------
__device__ __nv_bfloat16 g_xb[(size_t)N_TOK * HIDDEN];     // 16 MB
__device__ __nv_bfloat16 g_wb[(size_t)LATENT * HIDDEN];    // 32 MB
__device__ __half        g_z [(size_t)N_TOK * LATENT];     // 256 MB
__device__ int           g_cand[(size_t)N_TOK * NCAND];    // 2 MB
__device__ int           g_tidx[(size_t)N_TOK * TOPK];
__device__ float         g_tval[(size_t)N_TOK * TOPK];
__device__ float         g_wdt[(size_t)LATENT * HIDDEN];   // 64 MB (W_dec transposed)

// ---------------- fp32 -> bf16 converts ----------------
__global__ void cvt_x_kernel(const float4* __restrict__ src, int n4) {
    int i = blockIdx.x * blockDim.x + threadIdx.x;
    if (i >= n4) return;
    float4 f = src[i];
    __nv_bfloat162 h0 = __floats2bfloat162_rn(f.x, f.y);
    __nv_bfloat162 h1 = __floats2bfloat162_rn(f.z, f.w);
    uint2 o;
    o.x = *(const uint32_t*)&h0;
    o.y = *(const uint32_t*)&h1;
    *(uint2*)&g_xb[(size_t)i * 4] = o;
}

__global__ void cvt_w_kernel(const float4* __restrict__ src, int n4) {
    int i = blockIdx.x * blockDim.x + threadIdx.x;
    if (i >= n4) return;
    float4 f = src[i];
    __nv_bfloat162 h0 = __floats2bfloat162_rn(f.x, f.y);
    __nv_bfloat162 h1 = __floats2bfloat162_rn(f.z, f.w);
    uint2 o;
    o.x = *(const uint32_t*)&h0;
    o.y = *(const uint32_t*)&h1;
    *(uint2*)&g_wb[(size_t)i * 4] = o;
}

// ---------------- encode GEMM: z = x @ W_enc^T  (bf16 MMA, fp32 accum, fp16 store) ----------------
#define BM 128
#define BN 256
#define BK 32
#define KD HIDDEN
#define LDAS 40            // BK + 8 pad (80B rows: ldmatrix conflict-free, 16B aligned)

__global__ void __launch_bounds__(512, 1)
gemm_enc_kernel() {
    extern __shared__ __nv_bfloat16 sm[];
    const int SA_ELEMS = BM * LDAS;                 // 5120
    const int SB_ELEMS = BN * LDAS;                 // 10240
    const int STG = SA_ELEMS + SB_ELEMS;            // per stage

    const int tid  = threadIdx.x;
    const int lane = tid & 31;
    const int warp = tid >> 5;
    const int wr = warp >> 2;        // 0..3 -> 32 rows each
    const int wc = warp & 3;         // 0..3 -> 64 cols each
    const int bm = blockIdx.y * BM;
    const int bn = blockIdx.x * BN;

    // global load mapping: one uint4 (8 bf16) per row-slice
    const int gr = tid >> 2;         // 0..127
    const int gc = (tid & 3) * 8;    // 0,8,16,24

    const __nv_bfloat16* Ag = g_xb + (size_t)bm * KD;
    const __nv_bfloat16* Bg = g_wb + (size_t)bn * KD;

    float acc[2][8][4];
    #pragma unroll
    for (int i = 0; i < 2; i++)
        #pragma unroll
        for (int j = 0; j < 8; j++)
            #pragma unroll
            for (int q = 0; q < 4; q++) acc[i][j][q] = 0.f;

    uint4 ra, rb[2];
    // prologue: tile 0
    ra    = *(const uint4*)(Ag + (size_t)gr * KD + gc);
    rb[0] = *(const uint4*)(Bg + (size_t)gr * KD + gc);
    rb[1] = *(const uint4*)(Bg + (size_t)(gr + 128) * KD + gc);
    {
        __nv_bfloat16* sA = sm;
        __nv_bfloat16* sB = sm + SA_ELEMS;
        *(uint4*)(sA + gr * LDAS + gc) = ra;
        *(uint4*)(sB + gr * LDAS + gc) = rb[0];
        *(uint4*)(sB + (gr + 128) * LDAS + gc) = rb[1];
    }
    __syncthreads();

    const int NKT = KD / BK;   // 32
    for (int kt = 0; kt < NKT; ++kt) {
        const int cur = kt & 1;
        if (kt + 1 < NKT) {
            const int ko = (kt + 1) * BK;
            ra    = *(const uint4*)(Ag + (size_t)gr * KD + ko + gc);
            rb[0] = *(const uint4*)(Bg + (size_t)gr * KD + ko + gc);
            rb[1] = *(const uint4*)(Bg + (size_t)(gr + 128) * KD + ko + gc);
        }
        const __nv_bfloat16* sA = sm + cur * STG;
        const __nv_bfloat16* sB = sm + cur * STG + SA_ELEMS;
        uint32_t aBase = (uint32_t)__cvta_generic_to_shared(sA);
        uint32_t bBase = (uint32_t)__cvta_generic_to_shared(sB);

        #pragma unroll
        for (int ks = 0; ks < 2; ++ks) {
            const int kb = ks * 16;
            uint32_t afr[2][4];
            #pragma unroll
            for (int mi = 0; mi < 2; ++mi) {
                int row = wr * 32 + mi * 16 + (lane & 15);
                int col = kb + ((lane >> 4) << 3);
                uint32_t addr = aBase + (uint32_t)(row * LDAS + col) * 2;
                asm volatile("ldmatrix.sync.aligned.m8n8.x4.shared.b16 {%0,%1,%2,%3}, [%4];"
                    : "=r"(afr[mi][0]), "=r"(afr[mi][1]), "=r"(afr[mi][2]), "=r"(afr[mi][3])
                    : "r"(addr));
            }
            uint32_t bfr[8][2];
            #pragma unroll
            for (int j = 0; j < 4; ++j) {
                int n = wc * 64 + j * 16 + ((lane >> 4) << 3) + (lane & 7);
                int col = kb + (lane & 8);
                uint32_t addr = bBase + (uint32_t)(n * LDAS + col) * 2;
                asm volatile("ldmatrix.sync.aligned.m8n8.x4.shared.b16 {%0,%1,%2,%3}, [%4];"
                    : "=r"(bfr[2*j][0]), "=r"(bfr[2*j][1]), "=r"(bfr[2*j+1][0]), "=r"(bfr[2*j+1][1])
                    : "r"(addr));
            }
            #pragma unroll
            for (int mi = 0; mi < 2; ++mi)
                #pragma unroll
                for (int ni = 0; ni < 8; ++ni) {
                    asm volatile(
                        "mma.sync.aligned.m16n8k16.row.col.f32.bf16.bf16.f32 "
                        "{%0,%1,%2,%3},{%4,%5,%6,%7},{%8,%9},{%0,%1,%2,%3};"
                        : "+f"(acc[mi][ni][0]), "+f"(acc[mi][ni][1]),
                          "+f"(acc[mi][ni][2]), "+f"(acc[mi][ni][3])
                        : "r"(afr[mi][0]), "r"(afr[mi][1]), "r"(afr[mi][2]), "r"(afr[mi][3]),
                          "r"(bfr[ni][0]), "r"(bfr[ni][1]));
                }
        }
        if (kt + 1 < NKT) {
            __nv_bfloat16* dA = sm + ((kt + 1) & 1) * STG;
            __nv_bfloat16* dB = dA + SA_ELEMS;
            *(uint4*)(dA + gr * LDAS + gc) = ra;
            *(uint4*)(dB + gr * LDAS + gc) = rb[0];
            *(uint4*)(dB + (gr + 128) * LDAS + gc) = rb[1];
        }
        __syncthreads();
    }

    // epilogue: fp32 acc -> fp16 z
    const int grp = lane >> 2;
    const int qc  = (lane & 3) * 2;
    #pragma unroll
    for (int mi = 0; mi < 2; ++mi)
        #pragma unroll
        for (int ni = 0; ni < 8; ++ni) {
            int r0 = bm + wr * 32 + mi * 16 + grp;
            int c0 = bn + wc * 64 + ni * 8 + qc;
            __half2 h01 = __floats2half2_rn(acc[mi][ni][0], acc[mi][ni][1]);
            __half2 h23 = __floats2half2_rn(acc[mi][ni][2], acc[mi][ni][3]);
            *(__half2*)&g_z[(size_t)r0 * LATENT + c0] = h01;
            *(__half2*)&g_z[(size_t)(r0 + 8) * LATENT + c0] = h23;
        }
}

// ---------------- per-row top-64 candidates via 2-pass radix histogram on fp16 keys ----------------
__global__ void __launch_bounds__(256)
topk_cand_kernel() {
    __shared__ unsigned short keys[LATENT];          // 32 KB
    __shared__ unsigned int hist[256];
    __shared__ int s_b, s_k2;
    __shared__ unsigned int s_T;
    __shared__ int s_cnt;
    __shared__ int cand[NCAND];

    const int row = blockIdx.x;
    const int tid = threadIdx.x;
    if (tid < 256) hist[tid] = 0;
    if (tid == 0) s_cnt = 0;
    __syncthreads();

    const uint4* zr = (const uint4*)(g_z + (size_t)row * LATENT);
    for (int i = tid; i < LATENT / 8; i += 256) {
        uint4 v = zr[i];
        uint32_t w[4] = {v.x, v.y, v.z, v.w};
        #pragma unroll
        for (int q = 0; q < 4; ++q) {
            #pragma unroll
            for (int p = 0; p < 2; ++p) {
                unsigned short h = (unsigned short)((w[q] >> (16 * p)) & 0xFFFFu);
                unsigned short key = (h & 0x8000u) ? (unsigned short)(~h)
                                                   : (unsigned short)(h | 0x8000u);
                keys[i * 8 + q * 2 + p] = key;
                atomicAdd(&hist[key >> 8], 1u);
            }
        }
    }
    __syncthreads();
    if (tid == 0) {
        unsigned int c = 0; int b = 255;
        for (; b >= 0; --b) { c += hist[b]; if (c >= NCAND) break; }
        s_b  = b;
        s_k2 = NCAND - (int)(c - hist[b]);
    }
    __syncthreads();
    const int bsel = s_b, k2 = s_k2;
    if (tid < 256) hist[tid] = 0;
    __syncthreads();
    for (int i = tid; i < LATENT; i += 256) {
        unsigned short key = keys[i];
        if ((key >> 8) == (unsigned)bsel) atomicAdd(&hist[key & 255], 1u);
    }
    __syncthreads();
    if (tid == 0) {
        unsigned int c = 0; int l = 255;
        for (; l >= 0; --l) { c += hist[l]; if ((int)c >= k2) break; }
        s_T = ((unsigned)bsel << 8) | (unsigned)l;
    }
    __syncthreads();
    const unsigned int T = s_T;
    for (int i = tid; i < LATENT; i += 256) {
        if ((unsigned int)keys[i] > T) {
            int p = atomicAdd(&s_cnt, 1);
            cand[p] = i;
        }
    }
    __syncthreads();
    for (int i = tid; i < LATENT; i += 256) {
        if ((unsigned int)keys[i] == T) {
            int p = atomicAdd(&s_cnt, 1);
            if (p < NCAND) cand[p] = i;
        }
    }
    __syncthreads();
    if (tid < NCAND) g_cand[(size_t)row * NCAND + tid] = cand[tid];
}

// ---------------- exact fp32 recompute of 64 candidate dots + exact top-32 + scatter ----------------
__global__ void __launch_bounds__(256)
exact_topk_kernel(const float* __restrict__ x, const float* __restrict__ Wenc,
                  float* __restrict__ s_out) {
    __shared__ __align__(16) float xs[HIDDEN];
    __shared__ float vals[NCAND];
    __shared__ int   cand[NCAND];
    const int row  = blockIdx.x;
    const int tid  = threadIdx.x;
    const int lane = tid & 31;
    const int warp = tid >> 5;

    const float4* xr = (const float4*)(x + (size_t)row * HIDDEN);
    *(float4*)&xs[tid * 4] = xr[tid];
    if (tid < NCAND) cand[tid] = g_cand[(size_t)row * NCAND + tid];
    __syncthreads();

    for (int c = warp; c < NCAND; c += 8) {
        const float4* wrow = (const float4*)(Wenc + (size_t)cand[c] * HIDDEN);
        float a = 0.f;
        #pragma unroll
        for (int j = 0; j < 8; ++j) {
            float4 w4 = wrow[lane + 32 * j];
            float4 x4 = *(const float4*)&xs[(lane + 32 * j) * 4];
            a += w4.x * x4.x + w4.y * x4.y + w4.z * x4.z + w4.w * x4.w;
        }
        #pragma unroll
        for (int o = 16; o; o >>= 1) a += __shfl_xor_sync(0xffffffffu, a, o);
        if (lane == 0) vals[c] = a;
    }
    __syncthreads();

    if (warp == 0) {
        float v0 = vals[lane], v1 = vals[lane + 32];
        for (int t = 0; t < TOPK; ++t) {
            float lv = v0; int li = lane;
            if (v1 > lv) { lv = v1; li = lane + 32; }
            #pragma unroll
            for (int o = 16; o; o >>= 1) {
                float ov = __shfl_xor_sync(0xffffffffu, lv, o);
                int   oi = __shfl_xor_sync(0xffffffffu, li, o);
                if (ov > lv || (ov == lv && oi < li)) { lv = ov; li = oi; }
            }
            if (lane == 0) {
                int ci = cand[li];
                float rv = lv > 0.f ? lv : 0.f;
                s_out[(size_t)row * LATENT + ci] = rv;
                g_tidx[(size_t)row * TOPK + t] = ci;
                g_tval[(size_t)row * TOPK + t] = rv;
            }
            if ((li & 31) == lane) { if (li < 32) v0 = -1e30f; else v1 = -1e30f; }
        }
    }
}

// ---------------- W_dec transpose: [1024][16384] -> [16384][1024] ----------------
__global__ void transpose_wdec_kernel(const float* __restrict__ W) {
    __shared__ float t[32][33];
    const int bl = blockIdx.x * 32;   // latent
    const int bh = blockIdx.y * 32;   // hidden
    const int tx = threadIdx.x, ty = threadIdx.y;
    #pragma unroll
    for (int j = 0; j < 4; ++j)
        t[ty + 8 * j][tx] = W[(size_t)(bh + ty + 8 * j) * LATENT + bl + tx];
    __syncthreads();
    #pragma unroll
    for (int j = 0; j < 4; ++j)
        g_wdt[(size_t)(bl + ty + 8 * j) * HIDDEN + bh + tx] = t[tx][ty + 8 * j];
}

// ---------------- sparse decode: x_hat[n] = sum_k val_k * W_decT[idx_k] ----------------
__global__ void __launch_bounds__(256)
decode_kernel(float* __restrict__ xhat) {
    __shared__ int   sidx[TOPK];
    __shared__ float sval[TOPK];
    const int row = blockIdx.x;
    const int tid = threadIdx.x;
    if (tid < TOPK) {
        sidx[tid] = g_tidx[(size_t)row * TOPK + tid];
        sval[tid] = g_tval[(size_t)row * TOPK + tid];
    }
    __syncthreads();
    float a0 = 0.f, a1 = 0.f, a2 = 0.f, a3 = 0.f;
    #pragma unroll 4
    for (int k = 0; k < TOPK; ++k) {
        const float* wt = g_wdt + (size_t)sidx[k] * HIDDEN;
        float v = sval[k];
        a0 += v * wt[tid];
        a1 += v * wt[tid + 256];
        a2 += v * wt[tid + 512];
        a3 += v * wt[tid + 768];
    }
    float* o = xhat + (size_t)row * HIDDEN;
    o[tid] = a0; o[tid + 256] = a1; o[tid + 512] = a2; o[tid + 768] = a3;
}

// ---------------- launch ----------------
extern "C" void kernel_launch(void* const* d_in, const int* in_sizes, int n_in,
                              void* d_out, int out_size) {
    const float* x     = (const float*)d_in[0];
    const float* W_enc = (const float*)d_in[1];
    const float* W_dec = (const float*)d_in[2];
    float* xhat = (float*)d_out;
    float* s    = (float*)d_out + (size_t)N_TOK * HIDDEN;

    const int smem_gemm = (BM * LDAS + BN * LDAS) * 2 /*bf16*/ * 2 /*stages*/;  // 61440
    cudaFuncSetAttribute(gemm_enc_kernel, cudaFuncAttributeMaxDynamicSharedMemorySize, smem_gemm);

    // converts
    cvt_x_kernel<<<(N_TOK * HIDDEN / 4 + 255) / 256, 256>>>((const float4*)x, N_TOK * HIDDEN / 4);
    cvt_w_kernel<<<(LATENT * HIDDEN / 4 + 255) / 256, 256>>>((const float4*)W_enc, LATENT * HIDDEN / 4);

    // W_dec transpose (independent; needed before decode)
    transpose_wdec_kernel<<<dim3(LATENT / 32, HIDDEN / 32), dim3(32, 8)>>>(W_dec);

    // zero the sparse output region (scatter fills only top-k slots)
    cudaMemsetAsync(s, 0, (size_t)N_TOK * LATENT * sizeof(float), 0);

    // encode GEMM (bf16 candidates)
    gemm_enc_kernel<<<dim3(LATENT / BN, N_TOK / BM), 512, smem_gemm>>>();

    // top-64 candidates per row
    topk_cand_kernel<<<N_TOK, 256>>>();

    // exact fp32 recompute + top-32 select + scatter into s
    exact_topk_kernel<<<N_TOK, 256>>>(x, W_enc, s);

    // sparse decode
    decode_kernel<<<N_TOK, 256>>>(xhat);
}